// round 1
// baseline (speedup 1.0000x reference)
#include <cuda_runtime.h>
#include <cstddef>

#define D 128
#define K1 256
#define TILE 64
#define HP 132   // padded row length for h tile in smem

// 100000 * 128 floats of scratch for the aggregated messages (51.2 MB).
__device__ float g_agg[100000 * D];

__global__ void zero_agg_kernel(int n4) {
    float4 z = make_float4(0.f, 0.f, 0.f, 0.f);
    float4* p = reinterpret_cast<float4*>(g_agg);
    for (int i = blockIdx.x * blockDim.x + threadIdx.x; i < n4; i += gridDim.x * blockDim.x)
        p[i] = z;
}

// ---------------------------------------------------------------------------
// Edge kernel: for a tile of 64 edges
//   m = relu(concat(x[row], x[col]) @ w1 + b1) @ w2 + b2
//   atomicAdd into g_agg[col]
// 128 threads, each computes an 8(edge) x 8(out) register tile.
// ---------------------------------------------------------------------------
__global__ __launch_bounds__(128, 2)
void edge_kernel(const float* __restrict__ x, const int* __restrict__ ei, int E,
                 const float* __restrict__ w1, const float* __restrict__ b1,
                 const float* __restrict__ w2, const float* __restrict__ b2)
{
    extern __shared__ float sm[];          // 256*64 floats = 64 KB (reused)
    __shared__ int s_col[TILE];

    const int tid  = threadIdx.x;
    const int base = blockIdx.x * TILE;

    // ---- Gather: sm[k*64 + e] = concat(x[row_e], x[col_e])[k], k in [0,256)
    {
        const int e = tid & (TILE - 1);
        const int h = tid >> 6;            // 0: row half, 1: col half
        const int eidx = base + e;
        int src;
        if (h == 0) {
            src = (eidx < E) ? ei[eidx] : 0;
        } else {
            int c = (eidx < E) ? ei[E + eidx] : 0;
            s_col[e] = c;
            src = c;
        }
        const float4* __restrict__ xr = reinterpret_cast<const float4*>(x + (size_t)src * D);
        float* dst = sm + (h * D) * TILE + e;
        #pragma unroll
        for (int d4 = 0; d4 < D / 4; d4++) {
            float4 v = __ldg(xr + d4);
            dst[(d4 * 4 + 0) * TILE] = v.x;
            dst[(d4 * 4 + 1) * TILE] = v.y;
            dst[(d4 * 4 + 2) * TILE] = v.z;
            dst[(d4 * 4 + 3) * TILE] = v.w;
        }
    }
    __syncthreads();

    const int jg = tid & 15, eg = tid >> 4;
    const int j0 = jg * 8, e0 = eg * 8;

    // ---- GEMM1: [64,256] @ [256,128] + b1
    float acc[8][8];
    {
        float bj[8];
        #pragma unroll
        for (int j = 0; j < 8; j++) bj[j] = __ldg(b1 + j0 + j);
        #pragma unroll
        for (int e = 0; e < 8; e++)
            #pragma unroll
            for (int j = 0; j < 8; j++) acc[e][j] = bj[j];
    }
    #pragma unroll 2
    for (int k = 0; k < K1; k++) {
        float4 a0  = *reinterpret_cast<const float4*>(sm + k * TILE + e0);
        float4 a1  = *reinterpret_cast<const float4*>(sm + k * TILE + e0 + 4);
        float4 wv0 = __ldg(reinterpret_cast<const float4*>(w1 + k * D + j0));
        float4 wv1 = __ldg(reinterpret_cast<const float4*>(w1 + k * D + j0 + 4));
        float a[8] = {a0.x, a0.y, a0.z, a0.w, a1.x, a1.y, a1.z, a1.w};
        float w[8] = {wv0.x, wv0.y, wv0.z, wv0.w, wv1.x, wv1.y, wv1.z, wv1.w};
        #pragma unroll
        for (int e = 0; e < 8; e++)
            #pragma unroll
            for (int j = 0; j < 8; j++)
                acc[e][j] = fmaf(a[e], w[j], acc[e][j]);
    }
    __syncthreads();

    // ---- relu -> h tile sm[e*HP + j]
    #pragma unroll
    for (int e = 0; e < 8; e++) {
        #pragma unroll
        for (int j = 0; j < 8; j += 4) {
            float4 v;
            v.x = fmaxf(acc[e][j + 0], 0.f);
            v.y = fmaxf(acc[e][j + 1], 0.f);
            v.z = fmaxf(acc[e][j + 2], 0.f);
            v.w = fmaxf(acc[e][j + 3], 0.f);
            *reinterpret_cast<float4*>(sm + (e0 + e) * HP + j0 + j) = v;
        }
    }
    __syncthreads();

    // ---- GEMM2: [64,128] @ [128,128] + b2
    float acc2[8][8];
    {
        float bj[8];
        #pragma unroll
        for (int j = 0; j < 8; j++) bj[j] = __ldg(b2 + j0 + j);
        #pragma unroll
        for (int e = 0; e < 8; e++)
            #pragma unroll
            for (int j = 0; j < 8; j++) acc2[e][j] = bj[j];
    }
    #pragma unroll 2
    for (int k = 0; k < D; k++) {
        float4 wv0 = __ldg(reinterpret_cast<const float4*>(w2 + k * D + j0));
        float4 wv1 = __ldg(reinterpret_cast<const float4*>(w2 + k * D + j0 + 4));
        float w[8] = {wv0.x, wv0.y, wv0.z, wv0.w, wv1.x, wv1.y, wv1.z, wv1.w};
        float a[8];
        #pragma unroll
        for (int e = 0; e < 8; e++) a[e] = sm[(e0 + e) * HP + k];
        #pragma unroll
        for (int e = 0; e < 8; e++)
            #pragma unroll
            for (int j = 0; j < 8; j++)
                acc2[e][j] = fmaf(a[e], w[j], acc2[e][j]);
    }

    // ---- Scatter-add to destination nodes
    #pragma unroll
    for (int e = 0; e < 8; e++) {
        const int eidx = base + e0 + e;
        if (eidx < E) {
            float* dst = g_agg + (size_t)s_col[e0 + e] * D + j0;
            #pragma unroll
            for (int j = 0; j < 8; j++) atomicAdd(dst + j, acc2[e][j]);
        }
    }
}

// ---------------------------------------------------------------------------
// Node kernel: h = relu(concat(x, agg) @ wu1 + bu1) @ wu2 + bu2
//              out = layernorm(h)*gamma + beta + x
// ---------------------------------------------------------------------------
__global__ __launch_bounds__(128, 2)
void node_kernel(const float* __restrict__ x, int N,
                 const float* __restrict__ w1, const float* __restrict__ b1,
                 const float* __restrict__ w2, const float* __restrict__ b2,
                 const float* __restrict__ gamma, const float* __restrict__ beta,
                 float* __restrict__ out)
{
    extern __shared__ float sm[];
    const int tid  = threadIdx.x;
    const int base = blockIdx.x * TILE;

    // ---- Gather (contiguous rows): sm[k*64 + n] = concat(x[n], agg[n])[k]
    {
        const int e = tid & (TILE - 1);
        const int h = tid >> 6;
        const int node = base + e;
        float* dst = sm + (h * D) * TILE + e;
        if (node < N) {
            const float* src = (h == 0) ? (x + (size_t)node * D)
                                        : (g_agg + (size_t)node * D);
            const float4* sr = reinterpret_cast<const float4*>(src);
            #pragma unroll
            for (int d4 = 0; d4 < D / 4; d4++) {
                float4 v = __ldg(sr + d4);
                dst[(d4 * 4 + 0) * TILE] = v.x;
                dst[(d4 * 4 + 1) * TILE] = v.y;
                dst[(d4 * 4 + 2) * TILE] = v.z;
                dst[(d4 * 4 + 3) * TILE] = v.w;
            }
        } else {
            #pragma unroll
            for (int d = 0; d < D; d++) dst[d * TILE] = 0.f;
        }
    }
    __syncthreads();

    const int jg = tid & 15, eg = tid >> 4;
    const int j0 = jg * 8, e0 = eg * 8;

    // ---- GEMM1 + b1
    float acc[8][8];
    {
        float bj[8];
        #pragma unroll
        for (int j = 0; j < 8; j++) bj[j] = __ldg(b1 + j0 + j);
        #pragma unroll
        for (int e = 0; e < 8; e++)
            #pragma unroll
            for (int j = 0; j < 8; j++) acc[e][j] = bj[j];
    }
    #pragma unroll 2
    for (int k = 0; k < K1; k++) {
        float4 a0  = *reinterpret_cast<const float4*>(sm + k * TILE + e0);
        float4 a1  = *reinterpret_cast<const float4*>(sm + k * TILE + e0 + 4);
        float4 wv0 = __ldg(reinterpret_cast<const float4*>(w1 + k * D + j0));
        float4 wv1 = __ldg(reinterpret_cast<const float4*>(w1 + k * D + j0 + 4));
        float a[8] = {a0.x, a0.y, a0.z, a0.w, a1.x, a1.y, a1.z, a1.w};
        float w[8] = {wv0.x, wv0.y, wv0.z, wv0.w, wv1.x, wv1.y, wv1.z, wv1.w};
        #pragma unroll
        for (int e = 0; e < 8; e++)
            #pragma unroll
            for (int j = 0; j < 8; j++)
                acc[e][j] = fmaf(a[e], w[j], acc[e][j]);
    }
    __syncthreads();

    // ---- relu -> h tile
    #pragma unroll
    for (int e = 0; e < 8; e++) {
        #pragma unroll
        for (int j = 0; j < 8; j += 4) {
            float4 v;
            v.x = fmaxf(acc[e][j + 0], 0.f);
            v.y = fmaxf(acc[e][j + 1], 0.f);
            v.z = fmaxf(acc[e][j + 2], 0.f);
            v.w = fmaxf(acc[e][j + 3], 0.f);
            *reinterpret_cast<float4*>(sm + (e0 + e) * HP + j0 + j) = v;
        }
    }
    __syncthreads();

    // ---- GEMM2 + b2
    float acc2[8][8];
    {
        float bj[8];
        #pragma unroll
        for (int j = 0; j < 8; j++) bj[j] = __ldg(b2 + j0 + j);
        #pragma unroll
        for (int e = 0; e < 8; e++)
            #pragma unroll
            for (int j = 0; j < 8; j++) acc2[e][j] = bj[j];
    }
    #pragma unroll 2
    for (int k = 0; k < D; k++) {
        float4 wv0 = __ldg(reinterpret_cast<const float4*>(w2 + k * D + j0));
        float4 wv1 = __ldg(reinterpret_cast<const float4*>(w2 + k * D + j0 + 4));
        float w[8] = {wv0.x, wv0.y, wv0.z, wv0.w, wv1.x, wv1.y, wv1.z, wv1.w};
        float a[8];
        #pragma unroll
        for (int e = 0; e < 8; e++) a[e] = sm[(e0 + e) * HP + k];
        #pragma unroll
        for (int e = 0; e < 8; e++)
            #pragma unroll
            for (int j = 0; j < 8; j++)
                acc2[e][j] = fmaf(a[e], w[j], acc2[e][j]);
    }
    __syncthreads();

    // ---- store h back to smem (row-major, padded) for LayerNorm
    #pragma unroll
    for (int e = 0; e < 8; e++) {
        #pragma unroll
        for (int j = 0; j < 8; j += 4) {
            float4 v;
            v.x = acc2[e][j + 0];
            v.y = acc2[e][j + 1];
            v.z = acc2[e][j + 2];
            v.w = acc2[e][j + 3];
            *reinterpret_cast<float4*>(sm + (e0 + e) * HP + j0 + j) = v;
        }
    }
    __syncthreads();

    // ---- LayerNorm + residual; one thread per row
    if (tid < TILE) {
        const int node = base + tid;
        if (node < N) {
            const float* h = sm + tid * HP;
            float s = 0.f, s2 = 0.f;
            #pragma unroll
            for (int j = 0; j < D; j += 4) {
                float4 v = *reinterpret_cast<const float4*>(h + j);
                s  += v.x + v.y + v.z + v.w;
                s2 += v.x * v.x + v.y * v.y + v.z * v.z + v.w * v.w;
            }
            const float mu  = s * (1.f / D);
            const float var = s2 * (1.f / D) - mu * mu;
            const float inv = rsqrtf(var + 1e-5f);
            const float4* xr   = reinterpret_cast<const float4*>(x + (size_t)node * D);
            float4*       outr = reinterpret_cast<float4*>(out + (size_t)node * D);
            #pragma unroll
            for (int j = 0; j < D; j += 4) {
                float4 hv = *reinterpret_cast<const float4*>(h + j);
                float4 g  = __ldg(reinterpret_cast<const float4*>(gamma + j));
                float4 bt = __ldg(reinterpret_cast<const float4*>(beta + j));
                float4 xv = __ldg(xr + (j >> 2));
                float4 o;
                o.x = (hv.x - mu) * inv * g.x + bt.x + xv.x;
                o.y = (hv.y - mu) * inv * g.y + bt.y + xv.y;
                o.z = (hv.z - mu) * inv * g.z + bt.z + xv.z;
                o.w = (hv.w - mu) * inv * g.w + bt.w + xv.w;
                outr[j >> 2] = o;
            }
        }
    }
}

extern "C" void kernel_launch(void* const* d_in, const int* in_sizes, int n_in,
                              void* d_out, int out_size)
{
    const float* x     = (const float*)d_in[0];
    const int*   ei    = (const int*)  d_in[1];
    const float* w_m1  = (const float*)d_in[2];
    const float* b_m1  = (const float*)d_in[3];
    const float* w_m2  = (const float*)d_in[4];
    const float* b_m2  = (const float*)d_in[5];
    const float* w_u1  = (const float*)d_in[6];
    const float* b_u1  = (const float*)d_in[7];
    const float* w_u2  = (const float*)d_in[8];
    const float* b_u2  = (const float*)d_in[9];
    const float* gamma = (const float*)d_in[10];
    const float* beta  = (const float*)d_in[11];
    float* out = (float*)d_out;

    const int N = in_sizes[0] / D;
    const int E = in_sizes[1] / 2;
    const int SMEM = 2 * D * TILE * (int)sizeof(float);   // 64 KB

    cudaFuncSetAttribute(edge_kernel, cudaFuncAttributeMaxDynamicSharedMemorySize, SMEM);
    cudaFuncSetAttribute(node_kernel, cudaFuncAttributeMaxDynamicSharedMemorySize, SMEM);

    zero_agg_kernel<<<256, 256>>>((N * D) / 4);
    edge_kernel<<<(E + TILE - 1) / TILE, 128, SMEM>>>(x, ei, E, w_m1, b_m1, w_m2, b_m2);
    node_kernel<<<(N + TILE - 1) / TILE, 128, SMEM>>>(x, N, w_u1, b_u1, w_u2, b_u2,
                                                      gamma, beta, out);
}

// round 2
// speedup vs baseline: 1.0014x; 1.0014x over previous
#include <cuda_runtime.h>
#include <cstddef>

#define D 128
#define K1 256
#define TILE 64
#define HP 132   // padded row length for h tile in smem

// 100000 * 128 floats of scratch for the aggregated messages (51.2 MB).
__device__ float g_agg[100000 * D];

__global__ void zero_agg_kernel(int n4) {
    float4 z = make_float4(0.f, 0.f, 0.f, 0.f);
    float4* p = reinterpret_cast<float4*>(g_agg);
    for (int i = blockIdx.x * blockDim.x + threadIdx.x; i < n4; i += gridDim.x * blockDim.x)
        p[i] = z;
}

// ---------------------------------------------------------------------------
// Edge kernel: for a tile of 64 edges
//   m = relu(concat(x[row], x[col]) @ w1 + b1) @ w2 + b2
//   atomicAdd into g_agg[col]
// 128 threads, each computes an 8(edge) x 8(out) register tile.
// ---------------------------------------------------------------------------
__global__ __launch_bounds__(128, 2)
void edge_kernel(const float* __restrict__ x, const int* __restrict__ ei, int E,
                 const float* __restrict__ w1, const float* __restrict__ b1,
                 const float* __restrict__ w2, const float* __restrict__ b2)
{
    extern __shared__ float sm[];          // 256*64 floats = 64 KB (reused)
    __shared__ int s_col[TILE];

    const int tid  = threadIdx.x;
    const int base = blockIdx.x * TILE;

    // ---- Gather: sm[k*64 + e] = concat(x[row_e], x[col_e])[k], k in [0,256)
    {
        const int e = tid & (TILE - 1);
        const int h = tid >> 6;            // 0: row half, 1: col half
        const int eidx = base + e;
        int src;
        if (h == 0) {
            src = (eidx < E) ? ei[eidx] : 0;
        } else {
            int c = (eidx < E) ? ei[E + eidx] : 0;
            s_col[e] = c;
            src = c;
        }
        const float4* __restrict__ xr = reinterpret_cast<const float4*>(x + (size_t)src * D);
        float* dst = sm + (h * D) * TILE + e;
        #pragma unroll
        for (int d4 = 0; d4 < D / 4; d4++) {
            float4 v = __ldg(xr + d4);
            dst[(d4 * 4 + 0) * TILE] = v.x;
            dst[(d4 * 4 + 1) * TILE] = v.y;
            dst[(d4 * 4 + 2) * TILE] = v.z;
            dst[(d4 * 4 + 3) * TILE] = v.w;
        }
    }
    __syncthreads();

    const int jg = tid & 15, eg = tid >> 4;
    const int j0 = jg * 8, e0 = eg * 8;

    // ---- GEMM1: [64,256] @ [256,128] + b1
    float acc[8][8];
    {
        float bj[8];
        #pragma unroll
        for (int j = 0; j < 8; j++) bj[j] = __ldg(b1 + j0 + j);
        #pragma unroll
        for (int e = 0; e < 8; e++)
            #pragma unroll
            for (int j = 0; j < 8; j++) acc[e][j] = bj[j];
    }
    #pragma unroll 2
    for (int k = 0; k < K1; k++) {
        float4 a0  = *reinterpret_cast<const float4*>(sm + k * TILE + e0);
        float4 a1  = *reinterpret_cast<const float4*>(sm + k * TILE + e0 + 4);
        float4 wv0 = __ldg(reinterpret_cast<const float4*>(w1 + k * D + j0));
        float4 wv1 = __ldg(reinterpret_cast<const float4*>(w1 + k * D + j0 + 4));
        float a[8] = {a0.x, a0.y, a0.z, a0.w, a1.x, a1.y, a1.z, a1.w};
        float w[8] = {wv0.x, wv0.y, wv0.z, wv0.w, wv1.x, wv1.y, wv1.z, wv1.w};
        #pragma unroll
        for (int e = 0; e < 8; e++)
            #pragma unroll
            for (int j = 0; j < 8; j++)
                acc[e][j] = fmaf(a[e], w[j], acc[e][j]);
    }
    __syncthreads();

    // ---- relu -> h tile sm[e*HP + j]
    #pragma unroll
    for (int e = 0; e < 8; e++) {
        #pragma unroll
        for (int j = 0; j < 8; j += 4) {
            float4 v;
            v.x = fmaxf(acc[e][j + 0], 0.f);
            v.y = fmaxf(acc[e][j + 1], 0.f);
            v.z = fmaxf(acc[e][j + 2], 0.f);
            v.w = fmaxf(acc[e][j + 3], 0.f);
            *reinterpret_cast<float4*>(sm + (e0 + e) * HP + j0 + j) = v;
        }
    }
    __syncthreads();

    // ---- GEMM2: [64,128] @ [128,128] + b2
    float acc2[8][8];
    {
        float bj[8];
        #pragma unroll
        for (int j = 0; j < 8; j++) bj[j] = __ldg(b2 + j0 + j);
        #pragma unroll
        for (int e = 0; e < 8; e++)
            #pragma unroll
            for (int j = 0; j < 8; j++) acc2[e][j] = bj[j];
    }
    #pragma unroll 2
    for (int k = 0; k < D; k++) {
        float4 wv0 = __ldg(reinterpret_cast<const float4*>(w2 + k * D + j0));
        float4 wv1 = __ldg(reinterpret_cast<const float4*>(w2 + k * D + j0 + 4));
        float w[8] = {wv0.x, wv0.y, wv0.z, wv0.w, wv1.x, wv1.y, wv1.z, wv1.w};
        float a[8];
        #pragma unroll
        for (int e = 0; e < 8; e++) a[e] = sm[(e0 + e) * HP + k];
        #pragma unroll
        for (int e = 0; e < 8; e++)
            #pragma unroll
            for (int j = 0; j < 8; j++)
                acc2[e][j] = fmaf(a[e], w[j], acc2[e][j]);
    }

    // ---- Scatter-add to destination nodes
    #pragma unroll
    for (int e = 0; e < 8; e++) {
        const int eidx = base + e0 + e;
        if (eidx < E) {
            float* dst = g_agg + (size_t)s_col[e0 + e] * D + j0;
            #pragma unroll
            for (int j = 0; j < 8; j++) atomicAdd(dst + j, acc2[e][j]);
        }
    }
}

// ---------------------------------------------------------------------------
// Node kernel: h = relu(concat(x, agg) @ wu1 + bu1) @ wu2 + bu2
//              out = layernorm(h)*gamma + beta + x
// ---------------------------------------------------------------------------
__global__ __launch_bounds__(128, 2)
void node_kernel(const float* __restrict__ x, int N,
                 const float* __restrict__ w1, const float* __restrict__ b1,
                 const float* __restrict__ w2, const float* __restrict__ b2,
                 const float* __restrict__ gamma, const float* __restrict__ beta,
                 float* __restrict__ out)
{
    extern __shared__ float sm[];
    const int tid  = threadIdx.x;
    const int base = blockIdx.x * TILE;

    // ---- Gather (contiguous rows): sm[k*64 + n] = concat(x[n], agg[n])[k]
    {
        const int e = tid & (TILE - 1);
        const int h = tid >> 6;
        const int node = base + e;
        float* dst = sm + (h * D) * TILE + e;
        if (node < N) {
            const float* src = (h == 0) ? (x + (size_t)node * D)
                                        : (g_agg + (size_t)node * D);
            const float4* sr = reinterpret_cast<const float4*>(src);
            #pragma unroll
            for (int d4 = 0; d4 < D / 4; d4++) {
                float4 v = __ldg(sr + d4);
                dst[(d4 * 4 + 0) * TILE] = v.x;
                dst[(d4 * 4 + 1) * TILE] = v.y;
                dst[(d4 * 4 + 2) * TILE] = v.z;
                dst[(d4 * 4 + 3) * TILE] = v.w;
            }
        } else {
            #pragma unroll
            for (int d = 0; d < D; d++) dst[d * TILE] = 0.f;
        }
    }
    __syncthreads();

    const int jg = tid & 15, eg = tid >> 4;
    const int j0 = jg * 8, e0 = eg * 8;

    // ---- GEMM1 + b1
    float acc[8][8];
    {
        float bj[8];
        #pragma unroll
        for (int j = 0; j < 8; j++) bj[j] = __ldg(b1 + j0 + j);
        #pragma unroll
        for (int e = 0; e < 8; e++)
            #pragma unroll
            for (int j = 0; j < 8; j++) acc[e][j] = bj[j];
    }
    #pragma unroll 2
    for (int k = 0; k < K1; k++) {
        float4 a0  = *reinterpret_cast<const float4*>(sm + k * TILE + e0);
        float4 a1  = *reinterpret_cast<const float4*>(sm + k * TILE + e0 + 4);
        float4 wv0 = __ldg(reinterpret_cast<const float4*>(w1 + k * D + j0));
        float4 wv1 = __ldg(reinterpret_cast<const float4*>(w1 + k * D + j0 + 4));
        float a[8] = {a0.x, a0.y, a0.z, a0.w, a1.x, a1.y, a1.z, a1.w};
        float w[8] = {wv0.x, wv0.y, wv0.z, wv0.w, wv1.x, wv1.y, wv1.z, wv1.w};
        #pragma unroll
        for (int e = 0; e < 8; e++)
            #pragma unroll
            for (int j = 0; j < 8; j++)
                acc[e][j] = fmaf(a[e], w[j], acc[e][j]);
    }
    __syncthreads();

    // ---- relu -> h tile
    #pragma unroll
    for (int e = 0; e < 8; e++) {
        #pragma unroll
        for (int j = 0; j < 8; j += 4) {
            float4 v;
            v.x = fmaxf(acc[e][j + 0], 0.f);
            v.y = fmaxf(acc[e][j + 1], 0.f);
            v.z = fmaxf(acc[e][j + 2], 0.f);
            v.w = fmaxf(acc[e][j + 3], 0.f);
            *reinterpret_cast<float4*>(sm + (e0 + e) * HP + j0 + j) = v;
        }
    }
    __syncthreads();

    // ---- GEMM2 + b2
    float acc2[8][8];
    {
        float bj[8];
        #pragma unroll
        for (int j = 0; j < 8; j++) bj[j] = __ldg(b2 + j0 + j);
        #pragma unroll
        for (int e = 0; e < 8; e++)
            #pragma unroll
            for (int j = 0; j < 8; j++) acc2[e][j] = bj[j];
    }
    #pragma unroll 2
    for (int k = 0; k < D; k++) {
        float4 wv0 = __ldg(reinterpret_cast<const float4*>(w2 + k * D + j0));
        float4 wv1 = __ldg(reinterpret_cast<const float4*>(w2 + k * D + j0 + 4));
        float w[8] = {wv0.x, wv0.y, wv0.z, wv0.w, wv1.x, wv1.y, wv1.z, wv1.w};
        float a[8];
        #pragma unroll
        for (int e = 0; e < 8; e++) a[e] = sm[(e0 + e) * HP + k];
        #pragma unroll
        for (int e = 0; e < 8; e++)
            #pragma unroll
            for (int j = 0; j < 8; j++)
                acc2[e][j] = fmaf(a[e], w[j], acc2[e][j]);
    }
    __syncthreads();

    // ---- store h back to smem (row-major, padded) for LayerNorm
    #pragma unroll
    for (int e = 0; e < 8; e++) {
        #pragma unroll
        for (int j = 0; j < 8; j += 4) {
            float4 v;
            v.x = acc2[e][j + 0];
            v.y = acc2[e][j + 1];
            v.z = acc2[e][j + 2];
            v.w = acc2[e][j + 3];
            *reinterpret_cast<float4*>(sm + (e0 + e) * HP + j0 + j) = v;
        }
    }
    __syncthreads();

    // ---- LayerNorm + residual; one thread per row
    if (tid < TILE) {
        const int node = base + tid;
        if (node < N) {
            const float* h = sm + tid * HP;
            float s = 0.f, s2 = 0.f;
            #pragma unroll
            for (int j = 0; j < D; j += 4) {
                float4 v = *reinterpret_cast<const float4*>(h + j);
                s  += v.x + v.y + v.z + v.w;
                s2 += v.x * v.x + v.y * v.y + v.z * v.z + v.w * v.w;
            }
            const float mu  = s * (1.f / D);
            const float var = s2 * (1.f / D) - mu * mu;
            const float inv = rsqrtf(var + 1e-5f);
            const float4* xr   = reinterpret_cast<const float4*>(x + (size_t)node * D);
            float4*       outr = reinterpret_cast<float4*>(out + (size_t)node * D);
            #pragma unroll
            for (int j = 0; j < D; j += 4) {
                float4 hv = *reinterpret_cast<const float4*>(h + j);
                float4 g  = __ldg(reinterpret_cast<const float4*>(gamma + j));
                float4 bt = __ldg(reinterpret_cast<const float4*>(beta + j));
                float4 xv = __ldg(xr + (j >> 2));
                float4 o;
                o.x = (hv.x - mu) * inv * g.x + bt.x + xv.x;
                o.y = (hv.y - mu) * inv * g.y + bt.y + xv.y;
                o.z = (hv.z - mu) * inv * g.z + bt.z + xv.z;
                o.w = (hv.w - mu) * inv * g.w + bt.w + xv.w;
                outr[j >> 2] = o;
            }
        }
    }
}

extern "C" void kernel_launch(void* const* d_in, const int* in_sizes, int n_in,
                              void* d_out, int out_size)
{
    const float* x     = (const float*)d_in[0];
    const int*   ei    = (const int*)  d_in[1];
    const float* w_m1  = (const float*)d_in[2];
    const float* b_m1  = (const float*)d_in[3];
    const float* w_m2  = (const float*)d_in[4];
    const float* b_m2  = (const float*)d_in[5];
    const float* w_u1  = (const float*)d_in[6];
    const float* b_u1  = (const float*)d_in[7];
    const float* w_u2  = (const float*)d_in[8];
    const float* b_u2  = (const float*)d_in[9];
    const float* gamma = (const float*)d_in[10];
    const float* beta  = (const float*)d_in[11];
    float* out = (float*)d_out;

    const int N = in_sizes[0] / D;
    const int E = in_sizes[1] / 2;
    const int SMEM = 2 * D * TILE * (int)sizeof(float);   // 64 KB

    cudaFuncSetAttribute(edge_kernel, cudaFuncAttributeMaxDynamicSharedMemorySize, SMEM);
    cudaFuncSetAttribute(node_kernel, cudaFuncAttributeMaxDynamicSharedMemorySize, SMEM);

    zero_agg_kernel<<<256, 256>>>((N * D) / 4);
    edge_kernel<<<(E + TILE - 1) / TILE, 128, SMEM>>>(x, ei, E, w_m1, b_m1, w_m2, b_m2);
    node_kernel<<<(N + TILE - 1) / TILE, 128, SMEM>>>(x, N, w_u1, b_u1, w_u2, b_u2,
                                                      gamma, beta, out);
}

// round 7
// speedup vs baseline: 3.1699x; 3.1654x over previous
#include <cuda_runtime.h>
#include <cstdint>
#include <cstddef>

#define D 128
#define NMAX 100000
#define PAD1 260   // A1 row stride (words); 260 % 32 == 4 -> conflict-free frag LDS
#define PAD2 132   // H row stride (words);  132 % 32 == 4

// ---------------- device scratch (no allocs allowed) ----------------
__device__ float g_agg[NMAX * D];      // 51.2 MB aggregation buffer
__device__ float g_w1f[32 * 16 * 64];  // w_m1 fragment image (tf32), [s][nb][lane][2]
__device__ float g_w2f[16 * 16 * 64];  // w_m2 fragment image
__device__ float g_u1f[32 * 16 * 64];  // w_u1 fragment image
__device__ float g_u2f[16 * 16 * 64];  // w_u2 fragment image

// ---------------- helpers ----------------
__device__ __forceinline__ float tf32r(float x) {
    uint32_t u;
    asm("cvt.rna.tf32.f32 %0, %1;" : "=r"(u) : "f"(x));
    return __uint_as_float(u);
}
__device__ __forceinline__ void mma8(float* c, const uint32_t* a, float2 b) {
    uint32_t b0 = __float_as_uint(b.x), b1 = __float_as_uint(b.y);
    asm volatile(
        "mma.sync.aligned.m16n8k8.row.col.f32.tf32.tf32.f32 "
        "{%0,%1,%2,%3}, {%4,%5,%6,%7}, {%8,%9}, {%0,%1,%2,%3};"
        : "+f"(c[0]), "+f"(c[1]), "+f"(c[2]), "+f"(c[3])
        : "r"(a[0]), "r"(a[1]), "r"(a[2]), "r"(a[3]), "r"(b0), "r"(b1));
}
__device__ __forceinline__ void red2(float* p, float a, float b) {
    asm volatile("red.global.add.v2.f32 [%0], {%1,%2};"
                 :: "l"(p), "f"(a), "f"(b) : "memory");
}

// ---------------- prep: weights -> tf32 fragment images ----------------
// out[((s*16+nb)*32+lane)*2+i] = tf32(w[(s*8 + (lane&3) + 4*i)*128 + nb*8 + (lane>>2)])
__global__ void prep_frag(const float* __restrict__ w, int S, int which) {
    float* out = (which == 0) ? g_w1f : (which == 1) ? g_w2f : (which == 2) ? g_u1f : g_u2f;
    int o = blockIdx.x * blockDim.x + threadIdx.x;
    if (o >= S * 16 * 64) return;
    int i = o & 1, lane = (o >> 1) & 31, nb = (o >> 6) & 15, s = o >> 10;
    int tig = lane & 3, g = lane >> 2;
    int k = s * 8 + tig + 4 * i;
    int n = nb * 8 + g;
    out[o] = tf32r(w[k * 128 + n]);
}

__global__ void zero_agg_kernel(int n4) {
    float4 z = make_float4(0.f, 0.f, 0.f, 0.f);
    float4* p = reinterpret_cast<float4*>(g_agg);
    for (int i = blockIdx.x * blockDim.x + threadIdx.x; i < n4; i += gridDim.x * blockDim.x)
        p[i] = z;
}

#define SMEM_WORDS (128 * PAD1)
#define SMEM_BYTES (SMEM_WORDS * 4)

// ---------------- edge kernel ----------------
__global__ __launch_bounds__(256, 1)
void edge_kernel(const float* __restrict__ x, const int* __restrict__ ei, int E,
                 const float* __restrict__ b1, const float* __restrict__ b2)
{
    extern __shared__ float sm[];                // A1 [128][PAD1]; reused as H [128][PAD2]
    __shared__ float s_b1[128], s_b2[128];
    __shared__ int s_col[128];

    const int tid = threadIdx.x, lane = tid & 31, wid = tid >> 5;
    const int g = lane >> 2, tig = lane & 3;
    const int warpM = wid & 3, warpN = wid >> 2;
    const int m0 = warpM * 32, n0 = warpN * 64;
    const int base = blockIdx.x * 128;

    if (tid < 128) { s_b1[tid] = b1[tid]; s_b2[tid] = b2[tid]; }

    // ---- gather concat(x[row], x[col]) with tf32 rounding
    {
        const int e = tid & 127, half = tid >> 7;
        const int eidx = base + e;
        const bool act = eidx < E;
        int src;
        if (half == 0) src = act ? ei[eidx] : 0;
        else { int cc = act ? ei[E + eidx] : 0; s_col[e] = cc; src = cc; }
        const float4* xp = (const float4*)(x + (size_t)src * D);
        float* dst = sm + e * PAD1 + half * 128;
        #pragma unroll
        for (int j = 0; j < 32; j++) {
            float4 v = __ldg(xp + j);
            float4 w;
            w.x = tf32r(v.x); w.y = tf32r(v.y); w.z = tf32r(v.z); w.w = tf32r(v.w);
            *(float4*)(dst + 4 * j) = w;
        }
    }
    __syncthreads();

    // ---- GEMM1: [128,256] @ w1 -> C (bias in accumulator init)
    float c[2][8][4];
    #pragma unroll
    for (int mt = 0; mt < 2; mt++)
        #pragma unroll
        for (int nb = 0; nb < 8; nb++) {
            int col = n0 + nb * 8 + tig * 2;
            c[mt][nb][0] = s_b1[col];
            c[mt][nb][1] = s_b1[col + 1];
            c[mt][nb][2] = c[mt][nb][0];
            c[mt][nb][3] = c[mt][nb][1];
        }
    {
        const float2* bf = (const float2*)g_w1f;
        float2 bc[8], bn[8];
        #pragma unroll
        for (int nb = 0; nb < 8; nb++)
            bc[nb] = __ldg(bf + (size_t)(warpN * 8 + nb) * 32 + lane);
        #pragma unroll 4
        for (int s = 0; s < 32; s++) {
            if (s < 31) {
                #pragma unroll
                for (int nb = 0; nb < 8; nb++)
                    bn[nb] = __ldg(bf + (size_t)((s + 1) * 16 + warpN * 8 + nb) * 32 + lane);
            }
            const int k0 = s * 8;
            uint32_t a[2][4];
            #pragma unroll
            for (int mt = 0; mt < 2; mt++) {
                const float* ar = sm + (m0 + mt * 16) * PAD1 + k0;
                a[mt][0] = __float_as_uint(ar[g * PAD1 + tig]);
                a[mt][1] = __float_as_uint(ar[(g + 8) * PAD1 + tig]);
                a[mt][2] = __float_as_uint(ar[g * PAD1 + tig + 4]);
                a[mt][3] = __float_as_uint(ar[(g + 8) * PAD1 + tig + 4]);
            }
            #pragma unroll
            for (int mt = 0; mt < 2; mt++)
                #pragma unroll
                for (int nb = 0; nb < 8; nb++)
                    mma8(c[mt][nb], a[mt], bc[nb]);
            #pragma unroll
            for (int nb = 0; nb < 8; nb++) bc[nb] = bn[nb];
        }
    }
    __syncthreads();

    // ---- relu + tf32 -> H [128][PAD2]
    #pragma unroll
    for (int mt = 0; mt < 2; mt++)
        #pragma unroll
        for (int nb = 0; nb < 8; nb++) {
            int col = n0 + nb * 8 + tig * 2;
            float2 v0, v1;
            v0.x = tf32r(fmaxf(c[mt][nb][0], 0.f));
            v0.y = tf32r(fmaxf(c[mt][nb][1], 0.f));
            v1.x = tf32r(fmaxf(c[mt][nb][2], 0.f));
            v1.y = tf32r(fmaxf(c[mt][nb][3], 0.f));
            *(float2*)(sm + (m0 + mt * 16 + g) * PAD2 + col) = v0;
            *(float2*)(sm + (m0 + mt * 16 + g + 8) * PAD2 + col) = v1;
        }
    __syncthreads();

    // ---- GEMM2: H @ w2 -> C (bias init)
    #pragma unroll
    for (int mt = 0; mt < 2; mt++)
        #pragma unroll
        for (int nb = 0; nb < 8; nb++) {
            int col = n0 + nb * 8 + tig * 2;
            c[mt][nb][0] = s_b2[col];
            c[mt][nb][1] = s_b2[col + 1];
            c[mt][nb][2] = c[mt][nb][0];
            c[mt][nb][3] = c[mt][nb][1];
        }
    {
        const float2* bf = (const float2*)g_w2f;
        float2 bc[8], bn[8];
        #pragma unroll
        for (int nb = 0; nb < 8; nb++)
            bc[nb] = __ldg(bf + (size_t)(warpN * 8 + nb) * 32 + lane);
        #pragma unroll 4
        for (int s = 0; s < 16; s++) {
            if (s < 15) {
                #pragma unroll
                for (int nb = 0; nb < 8; nb++)
                    bn[nb] = __ldg(bf + (size_t)((s + 1) * 16 + warpN * 8 + nb) * 32 + lane);
            }
            const int k0 = s * 8;
            uint32_t a[2][4];
            #pragma unroll
            for (int mt = 0; mt < 2; mt++) {
                const float* ar = sm + (m0 + mt * 16) * PAD2 + k0;
                a[mt][0] = __float_as_uint(ar[g * PAD2 + tig]);
                a[mt][1] = __float_as_uint(ar[(g + 8) * PAD2 + tig]);
                a[mt][2] = __float_as_uint(ar[g * PAD2 + tig + 4]);
                a[mt][3] = __float_as_uint(ar[(g + 8) * PAD2 + tig + 4]);
            }
            #pragma unroll
            for (int mt = 0; mt < 2; mt++)
                #pragma unroll
                for (int nb = 0; nb < 8; nb++)
                    mma8(c[mt][nb], a[mt], bc[nb]);
            #pragma unroll
            for (int nb = 0; nb < 8; nb++) bc[nb] = bn[nb];
        }
    }

    // ---- scatter-add m to g_agg[col] (vector no-return RED)
    #pragma unroll
    for (int mt = 0; mt < 2; mt++)
        #pragma unroll
        for (int rr = 0; rr < 2; rr++) {
            const int e = m0 + mt * 16 + g + rr * 8;
            if (base + e < E) {
                float* dst = g_agg + (size_t)s_col[e] * D + n0;
                #pragma unroll
                for (int nb = 0; nb < 8; nb++)
                    red2(dst + nb * 8 + tig * 2, c[mt][nb][rr * 2], c[mt][nb][rr * 2 + 1]);
            }
        }
}

// ---------------- node kernel ----------------
__global__ __launch_bounds__(256, 1)
void node_kernel(const float* __restrict__ x, int N,
                 const float* __restrict__ b1, const float* __restrict__ b2,
                 const float* __restrict__ gamma, const float* __restrict__ beta,
                 float* __restrict__ out)
{
    extern __shared__ float sm[];
    __shared__ float s_b1[128], s_b2[128], s_g[128], s_be[128];

    const int tid = threadIdx.x, lane = tid & 31, wid = tid >> 5;
    const int g = lane >> 2, tig = lane & 3;
    const int warpM = wid & 3, warpN = wid >> 2;
    const int m0 = warpM * 32, n0 = warpN * 64;
    const int base = blockIdx.x * 128;

    if (tid < 128) {
        s_b1[tid] = b1[tid]; s_b2[tid] = b2[tid];
        s_g[tid] = gamma[tid]; s_be[tid] = beta[tid];
    }

    // ---- gather concat(x[n], agg[n]) with tf32 rounding
    {
        const int r = tid & 127, half = tid >> 7;
        const int node = base + r;
        const int src = (node < N) ? node : 0;
        const float* srcp = (half == 0) ? (x + (size_t)src * D) : (g_agg + (size_t)src * D);
        const float4* xp = (const float4*)srcp;
        float* dst = sm + r * PAD1 + half * 128;
        #pragma unroll
        for (int j = 0; j < 32; j++) {
            float4 v = __ldg(xp + j);
            float4 w;
            w.x = tf32r(v.x); w.y = tf32r(v.y); w.z = tf32r(v.z); w.w = tf32r(v.w);
            *(float4*)(dst + 4 * j) = w;
        }
    }
    __syncthreads();

    // ---- GEMM1
    float c[2][8][4];
    #pragma unroll
    for (int mt = 0; mt < 2; mt++)
        #pragma unroll
        for (int nb = 0; nb < 8; nb++) {
            int col = n0 + nb * 8 + tig * 2;
            c[mt][nb][0] = s_b1[col];
            c[mt][nb][1] = s_b1[col + 1];
            c[mt][nb][2] = c[mt][nb][0];
            c[mt][nb][3] = c[mt][nb][1];
        }
    {
        const float2* bf = (const float2*)g_u1f;
        float2 bc[8], bn[8];
        #pragma unroll
        for (int nb = 0; nb < 8; nb++)
            bc[nb] = __ldg(bf + (size_t)(warpN * 8 + nb) * 32 + lane);
        #pragma unroll 4
        for (int s = 0; s < 32; s++) {
            if (s < 31) {
                #pragma unroll
                for (int nb = 0; nb < 8; nb++)
                    bn[nb] = __ldg(bf + (size_t)((s + 1) * 16 + warpN * 8 + nb) * 32 + lane);
            }
            const int k0 = s * 8;
            uint32_t a[2][4];
            #pragma unroll
            for (int mt = 0; mt < 2; mt++) {
                const float* ar = sm + (m0 + mt * 16) * PAD1 + k0;
                a[mt][0] = __float_as_uint(ar[g * PAD1 + tig]);
                a[mt][1] = __float_as_uint(ar[(g + 8) * PAD1 + tig]);
                a[mt][2] = __float_as_uint(ar[g * PAD1 + tig + 4]);
                a[mt][3] = __float_as_uint(ar[(g + 8) * PAD1 + tig + 4]);
            }
            #pragma unroll
            for (int mt = 0; mt < 2; mt++)
                #pragma unroll
                for (int nb = 0; nb < 8; nb++)
                    mma8(c[mt][nb], a[mt], bc[nb]);
            #pragma unroll
            for (int nb = 0; nb < 8; nb++) bc[nb] = bn[nb];
        }
    }
    __syncthreads();

    // ---- relu + tf32 -> H
    #pragma unroll
    for (int mt = 0; mt < 2; mt++)
        #pragma unroll
        for (int nb = 0; nb < 8; nb++) {
            int col = n0 + nb * 8 + tig * 2;
            float2 v0, v1;
            v0.x = tf32r(fmaxf(c[mt][nb][0], 0.f));
            v0.y = tf32r(fmaxf(c[mt][nb][1], 0.f));
            v1.x = tf32r(fmaxf(c[mt][nb][2], 0.f));
            v1.y = tf32r(fmaxf(c[mt][nb][3], 0.f));
            *(float2*)(sm + (m0 + mt * 16 + g) * PAD2 + col) = v0;
            *(float2*)(sm + (m0 + mt * 16 + g + 8) * PAD2 + col) = v1;
        }
    __syncthreads();

    // ---- GEMM2
    #pragma unroll
    for (int mt = 0; mt < 2; mt++)
        #pragma unroll
        for (int nb = 0; nb < 8; nb++) {
            int col = n0 + nb * 8 + tig * 2;
            c[mt][nb][0] = s_b2[col];
            c[mt][nb][1] = s_b2[col + 1];
            c[mt][nb][2] = c[mt][nb][0];
            c[mt][nb][3] = c[mt][nb][1];
        }
    {
        const float2* bf = (const float2*)g_u2f;
        float2 bc[8], bn[8];
        #pragma unroll
        for (int nb = 0; nb < 8; nb++)
            bc[nb] = __ldg(bf + (size_t)(warpN * 8 + nb) * 32 + lane);
        #pragma unroll 4
        for (int s = 0; s < 16; s++) {
            if (s < 15) {
                #pragma unroll
                for (int nb = 0; nb < 8; nb++)
                    bn[nb] = __ldg(bf + (size_t)((s + 1) * 16 + warpN * 8 + nb) * 32 + lane);
            }
            const int k0 = s * 8;
            uint32_t a[2][4];
            #pragma unroll
            for (int mt = 0; mt < 2; mt++) {
                const float* ar = sm + (m0 + mt * 16) * PAD2 + k0;
                a[mt][0] = __float_as_uint(ar[g * PAD2 + tig]);
                a[mt][1] = __float_as_uint(ar[(g + 8) * PAD2 + tig]);
                a[mt][2] = __float_as_uint(ar[g * PAD2 + tig + 4]);
                a[mt][3] = __float_as_uint(ar[(g + 8) * PAD2 + tig + 4]);
            }
            #pragma unroll
            for (int mt = 0; mt < 2; mt++)
                #pragma unroll
                for (int nb = 0; nb < 8; nb++)
                    mma8(c[mt][nb], a[mt], bc[nb]);
            #pragma unroll
            for (int nb = 0; nb < 8; nb++) bc[nb] = bn[nb];
        }
    }
    __syncthreads();

    // ---- store h (fp32, no rounding) to H for the LN epilogue
    #pragma unroll
    for (int mt = 0; mt < 2; mt++)
        #pragma unroll
        for (int nb = 0; nb < 8; nb++) {
            int col = n0 + nb * 8 + tig * 2;
            float2 v0, v1;
            v0.x = c[mt][nb][0]; v0.y = c[mt][nb][1];
            v1.x = c[mt][nb][2]; v1.y = c[mt][nb][3];
            *(float2*)(sm + (m0 + mt * 16 + g) * PAD2 + col) = v0;
            *(float2*)(sm + (m0 + mt * 16 + g + 8) * PAD2 + col) = v1;
        }
    __syncthreads();

    // ---- LayerNorm + residual: 2 threads per row
    {
        const int r = tid >> 1, half = tid & 1;
        const int node = base + r;
        const float* hr = sm + r * PAD2 + half * 64;
        float s1 = 0.f, s2 = 0.f;
        #pragma unroll
        for (int j = 0; j < 64; j++) { float v = hr[j]; s1 += v; s2 += v * v; }
        s1 += __shfl_xor_sync(0xFFFFFFFFu, s1, 1);
        s2 += __shfl_xor_sync(0xFFFFFFFFu, s2, 1);
        const float mu  = s1 * (1.f / 128.f);
        const float var = s2 * (1.f / 128.f) - mu * mu;
        const float inv = rsqrtf(var + 1e-5f);
        if (node < N) {
            const float4* xp = (const float4*)(x + (size_t)node * D + half * 64);
            float4* op = (float4*)(out + (size_t)node * D + half * 64);
            #pragma unroll
            for (int j = 0; j < 16; j++) {
                float4 h4 = *(const float4*)(hr + 4 * j);
                float4 gv = *(const float4*)(s_g + half * 64 + 4 * j);
                float4 bv = *(const float4*)(s_be + half * 64 + 4 * j);
                float4 xv = __ldg(xp + j);
                float4 o;
                o.x = (h4.x - mu) * inv * gv.x + bv.x + xv.x;
                o.y = (h4.y - mu) * inv * gv.y + bv.y + xv.y;
                o.z = (h4.z - mu) * inv * gv.z + bv.z + xv.z;
                o.w = (h4.w - mu) * inv * gv.w + bv.w + xv.w;
                op[j] = o;
            }
        }
    }
}

// ---------------- launch ----------------
extern "C" void kernel_launch(void* const* d_in, const int* in_sizes, int n_in,
                              void* d_out, int out_size)
{
    const float* x     = (const float*)d_in[0];
    const int*   ei    = (const int*)  d_in[1];
    const float* w_m1  = (const float*)d_in[2];
    const float* b_m1  = (const float*)d_in[3];
    const float* w_m2  = (const float*)d_in[4];
    const float* b_m2  = (const float*)d_in[5];
    const float* w_u1  = (const float*)d_in[6];
    const float* b_u1  = (const float*)d_in[7];
    const float* w_u2  = (const float*)d_in[8];
    const float* b_u2  = (const float*)d_in[9];
    const float* gamma = (const float*)d_in[10];
    const float* beta  = (const float*)d_in[11];
    float* out = (float*)d_out;

    const int N = in_sizes[0] / D;
    const int E = in_sizes[1] / 2;
    const int ntiles_e = (E + 127) / 128;
    const int ntiles_n = (N + 127) / 128;

    cudaFuncSetAttribute(edge_kernel, cudaFuncAttributeMaxDynamicSharedMemorySize, SMEM_BYTES);
    cudaFuncSetAttribute(node_kernel, cudaFuncAttributeMaxDynamicSharedMemorySize, SMEM_BYTES);

    prep_frag<<<(32 * 16 * 64 + 255) / 256, 256>>>(w_m1, 32, 0);
    prep_frag<<<(16 * 16 * 64 + 255) / 256, 256>>>(w_m2, 16, 1);
    prep_frag<<<(32 * 16 * 64 + 255) / 256, 256>>>(w_u1, 32, 2);
    prep_frag<<<(16 * 16 * 64 + 255) / 256, 256>>>(w_u2, 16, 3);
    zero_agg_kernel<<<1024, 256>>>((N * D) / 4);
    edge_kernel<<<ntiles_e, 256, SMEM_BYTES>>>(x, ei, E, b_m1, b_m2);
    node_kernel<<<ntiles_n, 256, SMEM_BYTES>>>(x, N, b_u1, b_u2, gamma, beta, out);
}

// round 11
// speedup vs baseline: 3.7819x; 1.1931x over previous
#include <cuda_runtime.h>
#include <cstdint>
#include <cstddef>

#define D 128
#define NMAX 100000
#define PAD2 132   // row stride (words); 132 % 32 == 4 -> conflict-free frag LDS

// ---------------- device scratch (no allocs allowed) ----------------
__device__ float g_agg[NMAX * D];      // 51.2 MB aggregation buffer
__device__ float g_w1f[32 * 16 * 64];  // w_m1 fragment image (tf32), [s][nb][lane][2]
__device__ float g_w2f[16 * 16 * 64];  // w_m2 fragment image
__device__ float g_u1f[32 * 16 * 64];  // w_u1 fragment image
__device__ float g_u2f[16 * 16 * 64];  // w_u2 fragment image

// ---------------- helpers ----------------
__device__ __forceinline__ float tf32r(float x) {
    uint32_t u;
    asm("cvt.rna.tf32.f32 %0, %1;" : "=r"(u) : "f"(x));
    return __uint_as_float(u);
}
__device__ __forceinline__ void mma8(float* c, const uint32_t* a, float2 b) {
    uint32_t b0 = __float_as_uint(b.x), b1 = __float_as_uint(b.y);
    asm volatile(
        "mma.sync.aligned.m16n8k8.row.col.f32.tf32.tf32.f32 "
        "{%0,%1,%2,%3}, {%4,%5,%6,%7}, {%8,%9}, {%0,%1,%2,%3};"
        : "+f"(c[0]), "+f"(c[1]), "+f"(c[2]), "+f"(c[3])
        : "r"(a[0]), "r"(a[1]), "r"(a[2]), "r"(a[3]), "r"(b0), "r"(b1));
}
__device__ __forceinline__ void red2(float* p, float a, float b) {
    asm volatile("red.global.add.v2.f32 [%0], {%1,%2};"
                 :: "l"(p), "f"(a), "f"(b) : "memory");
}

// ---------------- prep: weights -> tf32 fragment images ----------------
// out[((s*16+nb)*32+lane)*2+i] = tf32(w[(s*8 + (lane&3) + 4*i)*128 + nb*8 + (lane>>2)])
__global__ void prep_frag(const float* __restrict__ w, int S, int which) {
    float* out = (which == 0) ? g_w1f : (which == 1) ? g_w2f : (which == 2) ? g_u1f : g_u2f;
    int o = blockIdx.x * blockDim.x + threadIdx.x;
    if (o >= S * 16 * 64) return;
    int i = o & 1, lane = (o >> 1) & 31, nb = (o >> 6) & 15, s = o >> 10;
    int tig = lane & 3, g = lane >> 2;
    int k = s * 8 + tig + 4 * i;
    int n = nb * 8 + g;
    out[o] = tf32r(w[k * 128 + n]);
}

__global__ void zero_agg_kernel(int n4) {
    float4 z = make_float4(0.f, 0.f, 0.f, 0.f);
    float4* p = reinterpret_cast<float4*>(g_agg);
    for (int i = blockIdx.x * blockDim.x + threadIdx.x; i < n4; i += gridDim.x * blockDim.x)
        p[i] = z;
}

#define SMEM_BYTES (128 * PAD2 * 4)   // 67584 B -> 2 CTAs/SM

// ---------------- shared building blocks ----------------
// gather one 128-wide half of the concat input into sm (tf32-rounded)
__device__ __forceinline__ void gather_half(float* sm, const float* __restrict__ srcbase,
                                            int tid) {
    const int e = tid >> 1, hh = tid & 1;
    const float4* xp = (const float4*)srcbase + hh * 16;
    float* dst = sm + e * PAD2 + hh * 64;
    #pragma unroll
    for (int j = 0; j < 16; j++) {
        float4 v = __ldg(xp + j);
        float4 w;
        w.x = tf32r(v.x); w.y = tf32r(v.y); w.z = tf32r(v.z); w.w = tf32r(v.w);
        *(float4*)(dst + 4 * j) = w;
    }
}

// accumulate nsteps k-steps of A(sm) @ B(frag image, starting kstep s0) into c
__device__ __forceinline__ void gemm_steps(float c[2][8][4], const float* sm,
                                           const float* __restrict__ wf,
                                           int s0, int nsteps,
                                           int m0, int warpN, int lane) {
    const int g = lane >> 2, tig = lane & 3;
    const float2* bf = (const float2*)wf;
    #pragma unroll 4
    for (int s = 0; s < nsteps; s++) {
        float2 bc[8];
        #pragma unroll
        for (int nb = 0; nb < 8; nb++)
            bc[nb] = __ldg(bf + (size_t)((s0 + s) * 16 + warpN * 8 + nb) * 32 + lane);
        const int k0 = s * 8;
        uint32_t a[2][4];
        #pragma unroll
        for (int mt = 0; mt < 2; mt++) {
            const float* ar = sm + (m0 + mt * 16) * PAD2 + k0;
            a[mt][0] = __float_as_uint(ar[g * PAD2 + tig]);
            a[mt][1] = __float_as_uint(ar[(g + 8) * PAD2 + tig]);
            a[mt][2] = __float_as_uint(ar[g * PAD2 + tig + 4]);
            a[mt][3] = __float_as_uint(ar[(g + 8) * PAD2 + tig + 4]);
        }
        #pragma unroll
        for (int mt = 0; mt < 2; mt++)
            #pragma unroll
            for (int nb = 0; nb < 8; nb++)
                mma8(c[mt][nb], a[mt], bc[nb]);
    }
}

__device__ __forceinline__ void init_bias(float c[2][8][4], const float* sb,
                                          int n0, int tig) {
    #pragma unroll
    for (int mt = 0; mt < 2; mt++)
        #pragma unroll
        for (int nb = 0; nb < 8; nb++) {
            int col = n0 + nb * 8 + tig * 2;
            c[mt][nb][0] = sb[col];
            c[mt][nb][1] = sb[col + 1];
            c[mt][nb][2] = c[mt][nb][0];
            c[mt][nb][3] = c[mt][nb][1];
        }
}

// ---------------- edge kernel ----------------
__global__ __launch_bounds__(256, 2)
void edge_kernel(const float* __restrict__ x, const int* __restrict__ ei, int E,
                 const float* __restrict__ b1, const float* __restrict__ b2)
{
    extern __shared__ float sm[];                // [128][PAD2], reused for A halves and H
    __shared__ float s_b1[128], s_b2[128];
    __shared__ int s_col[128];

    const int tid = threadIdx.x, lane = tid & 31, wid = tid >> 5;
    const int g = lane >> 2, tig = lane & 3;
    const int warpM = wid & 3, warpN = wid >> 2;
    const int m0 = warpM * 32, n0 = warpN * 64;
    const int base = blockIdx.x * 128;

    if (tid < 128) { s_b1[tid] = b1[tid]; s_b2[tid] = b2[tid]; }

    // ---- phase 0: gather x[row] half
    {
        const int e = tid >> 1;
        const int eidx = base + e;
        const int src = (eidx < E) ? ei[eidx] : 0;
        gather_half(sm, x + (size_t)src * D, tid);
    }
    __syncthreads();

    float c[2][8][4];
    init_bias(c, s_b1, n0, tig);
    gemm_steps(c, sm, g_w1f, 0, 16, m0, warpN, lane);
    __syncthreads();

    // ---- phase 1: gather x[col] half (also record dest col)
    {
        const int e = tid >> 1, hh = tid & 1;
        const int eidx = base + e;
        const int cc = (eidx < E) ? ei[E + eidx] : 0;
        if (hh == 0) s_col[e] = cc;
        gather_half(sm, x + (size_t)cc * D, tid);
    }
    __syncthreads();

    gemm_steps(c, sm, g_w1f, 16, 16, m0, warpN, lane);
    __syncthreads();

    // ---- relu + tf32 -> H
    #pragma unroll
    for (int mt = 0; mt < 2; mt++)
        #pragma unroll
        for (int nb = 0; nb < 8; nb++) {
            int col = n0 + nb * 8 + tig * 2;
            float2 v0, v1;
            v0.x = tf32r(fmaxf(c[mt][nb][0], 0.f));
            v0.y = tf32r(fmaxf(c[mt][nb][1], 0.f));
            v1.x = tf32r(fmaxf(c[mt][nb][2], 0.f));
            v1.y = tf32r(fmaxf(c[mt][nb][3], 0.f));
            *(float2*)(sm + (m0 + mt * 16 + g) * PAD2 + col) = v0;
            *(float2*)(sm + (m0 + mt * 16 + g + 8) * PAD2 + col) = v1;
        }
    __syncthreads();

    // ---- GEMM2
    init_bias(c, s_b2, n0, tig);
    gemm_steps(c, sm, g_w2f, 0, 16, m0, warpN, lane);

    // ---- scatter-add m to g_agg[col] (vector no-return RED)
    #pragma unroll
    for (int mt = 0; mt < 2; mt++)
        #pragma unroll
        for (int rr = 0; rr < 2; rr++) {
            const int e = m0 + mt * 16 + g + rr * 8;
            if (base + e < E) {
                float* dst = g_agg + (size_t)s_col[e] * D + n0;
                #pragma unroll
                for (int nb = 0; nb < 8; nb++)
                    red2(dst + nb * 8 + tig * 2, c[mt][nb][rr * 2], c[mt][nb][rr * 2 + 1]);
            }
        }
}

// ---------------- node kernel ----------------
__global__ __launch_bounds__(256, 2)
void node_kernel(const float* __restrict__ x, int N,
                 const float* __restrict__ b1, const float* __restrict__ b2,
                 const float* __restrict__ gamma, const float* __restrict__ beta,
                 float* __restrict__ out)
{
    extern __shared__ float sm[];
    __shared__ float s_b1[128], s_b2[128], s_g[128], s_be[128];

    const int tid = threadIdx.x, lane = tid & 31, wid = tid >> 5;
    const int g = lane >> 2, tig = lane & 3;
    const int warpM = wid & 3, warpN = wid >> 2;
    const int m0 = warpM * 32, n0 = warpN * 64;
    const int base = blockIdx.x * 128;

    if (tid < 128) {
        s_b1[tid] = b1[tid]; s_b2[tid] = b2[tid];
        s_g[tid] = gamma[tid]; s_be[tid] = beta[tid];
    }

    // ---- phase 0: gather x[node] half
    {
        const int r = tid >> 1;
        const int node = base + r;
        const int src = (node < N) ? node : 0;
        gather_half(sm, x + (size_t)src * D, tid);
    }
    __syncthreads();

    float c[2][8][4];
    init_bias(c, s_b1, n0, tig);
    gemm_steps(c, sm, g_u1f, 0, 16, m0, warpN, lane);
    __syncthreads();

    // ---- phase 1: gather agg[node] half
    {
        const int r = tid >> 1;
        const int node = base + r;
        const int src = (node < N) ? node : 0;
        gather_half(sm, g_agg + (size_t)src * D, tid);
    }
    __syncthreads();

    gemm_steps(c, sm, g_u1f, 16, 16, m0, warpN, lane);
    __syncthreads();

    // ---- relu + tf32 -> H
    #pragma unroll
    for (int mt = 0; mt < 2; mt++)
        #pragma unroll
        for (int nb = 0; nb < 8; nb++) {
            int col = n0 + nb * 8 + tig * 2;
            float2 v0, v1;
            v0.x = tf32r(fmaxf(c[mt][nb][0], 0.f));
            v0.y = tf32r(fmaxf(c[mt][nb][1], 0.f));
            v1.x = tf32r(fmaxf(c[mt][nb][2], 0.f));
            v1.y = tf32r(fmaxf(c[mt][nb][3], 0.f));
            *(float2*)(sm + (m0 + mt * 16 + g) * PAD2 + col) = v0;
            *(float2*)(sm + (m0 + mt * 16 + g + 8) * PAD2 + col) = v1;
        }
    __syncthreads();

    // ---- GEMM2
    init_bias(c, s_b2, n0, tig);
    gemm_steps(c, sm, g_u2f, 0, 16, m0, warpN, lane);
    __syncthreads();

    // ---- store h (fp32) to H for the LN epilogue
    #pragma unroll
    for (int mt = 0; mt < 2; mt++)
        #pragma unroll
        for (int nb = 0; nb < 8; nb++) {
            int col = n0 + nb * 8 + tig * 2;
            float2 v0, v1;
            v0.x = c[mt][nb][0]; v0.y = c[mt][nb][1];
            v1.x = c[mt][nb][2]; v1.y = c[mt][nb][3];
            *(float2*)(sm + (m0 + mt * 16 + g) * PAD2 + col) = v0;
            *(float2*)(sm + (m0 + mt * 16 + g + 8) * PAD2 + col) = v1;
        }
    __syncthreads();

    // ---- LayerNorm + residual: 2 threads per row
    {
        const int r = tid >> 1, half = tid & 1;
        const int node = base + r;
        const float* hr = sm + r * PAD2 + half * 64;
        float s1 = 0.f, s2 = 0.f;
        #pragma unroll
        for (int j = 0; j < 64; j++) { float v = hr[j]; s1 += v; s2 += v * v; }
        s1 += __shfl_xor_sync(0xFFFFFFFFu, s1, 1);
        s2 += __shfl_xor_sync(0xFFFFFFFFu, s2, 1);
        const float mu  = s1 * (1.f / 128.f);
        const float var = s2 * (1.f / 128.f) - mu * mu;
        const float inv = rsqrtf(var + 1e-5f);
        if (node < N) {
            const float4* xp = (const float4*)(x + (size_t)node * D + half * 64);
            float4* op = (float4*)(out + (size_t)node * D + half * 64);
            #pragma unroll
            for (int j = 0; j < 16; j++) {
                float4 h4 = *(const float4*)(hr + 4 * j);
                float4 gv = *(const float4*)(s_g + half * 64 + 4 * j);
                float4 bv = *(const float4*)(s_be + half * 64 + 4 * j);
                float4 xv = __ldg(xp + j);
                float4 o;
                o.x = (h4.x - mu) * inv * gv.x + bv.x + xv.x;
                o.y = (h4.y - mu) * inv * gv.y + bv.y + xv.y;
                o.z = (h4.z - mu) * inv * gv.z + bv.z + xv.z;
                o.w = (h4.w - mu) * inv * gv.w + bv.w + xv.w;
                op[j] = o;
            }
        }
    }
}

// ---------------- launch ----------------
extern "C" void kernel_launch(void* const* d_in, const int* in_sizes, int n_in,
                              void* d_out, int out_size)
{
    const float* x     = (const float*)d_in[0];
    const int*   ei    = (const int*)  d_in[1];
    const float* w_m1  = (const float*)d_in[2];
    const float* b_m1  = (const float*)d_in[3];
    const float* w_m2  = (const float*)d_in[4];
    const float* b_m2  = (const float*)d_in[5];
    const float* w_u1  = (const float*)d_in[6];
    const float* b_u1  = (const float*)d_in[7];
    const float* w_u2  = (const float*)d_in[8];
    const float* b_u2  = (const float*)d_in[9];
    const float* gamma = (const float*)d_in[10];
    const float* beta  = (const float*)d_in[11];
    float* out = (float*)d_out;

    const int N = in_sizes[0] / D;
    const int E = in_sizes[1] / 2;
    const int ntiles_e = (E + 127) / 128;
    const int ntiles_n = (N + 127) / 128;

    cudaFuncSetAttribute(edge_kernel, cudaFuncAttributeMaxDynamicSharedMemorySize, SMEM_BYTES);
    cudaFuncSetAttribute(node_kernel, cudaFuncAttributeMaxDynamicSharedMemorySize, SMEM_BYTES);

    prep_frag<<<(32 * 16 * 64 + 255) / 256, 256>>>(w_m1, 32, 0);
    prep_frag<<<(16 * 16 * 64 + 255) / 256, 256>>>(w_m2, 16, 1);
    prep_frag<<<(32 * 16 * 64 + 255) / 256, 256>>>(w_u1, 32, 2);
    prep_frag<<<(16 * 16 * 64 + 255) / 256, 256>>>(w_u2, 16, 3);
    zero_agg_kernel<<<1024, 256>>>((N * D) / 4);
    edge_kernel<<<ntiles_e, 256, SMEM_BYTES>>>(x, ei, E, b_m1, b_m2);
    node_kernel<<<ntiles_n, 256, SMEM_BYTES>>>(x, N, b_u1, b_u2, gamma, beta, out);
}